// round 7
// baseline (speedup 1.0000x reference)
#include <cuda_runtime.h>
#include <cooperative_groups.h>
#include <cstdint>

namespace cg = cooperative_groups;

namespace {
constexpr int   kB       = 8;
constexpr int   kNT      = 256;
constexpr int   kNZ      = 256;
constexpr int   kNX      = 256;
constexpr int   kNREC    = 64;
constexpr int   kThreads = 512;           // column = tid&255, half = tid>>8
constexpr float kDT2     = 1.0e-6f;       // DT*DT
constexpr float kInvDH2  = 0.01f;         // 1/(DH*DH)

// smem (floats): vEdge[2][4][256]=2048 | hEdge[2][2][8][R][2]=64R | wav[256] | rz[64] | rx[64]
constexpr int smem_floats(int cluster) {
    int R = kNZ / cluster / 2;
    return 2048 + 64 * R + kNT + 64 + 64;
}
constexpr int smem_bytes(int cluster) { return smem_floats(cluster) * 4; }
}

#define CLUSTER_ARRIVE() asm volatile("barrier.cluster.arrive.aligned;" ::: "memory")
#define CLUSTER_WAIT()   asm volatile("barrier.cluster.wait.aligned;"   ::: "memory")

template <int CLUSTER>
__global__ void __launch_bounds__(kThreads, 1)
wave_fd_kernel(const float* __restrict__ x,
               const float* __restrict__ vp,
               const int*   __restrict__ src_loc,
               const int*   __restrict__ rec_loc,
               float*       __restrict__ out)
{
    constexpr int kRows  = kNZ / CLUSTER;   // rows per CTA
    constexpr int R      = kRows / 2;       // rows per thread (register-resident)
    constexpr int HE_OFF = 2048;
    constexpr int WAV_OFF = HE_OFF + 64 * R;
    constexpr int RZ_OFF  = WAV_OFF + kNT;
    constexpr int RX_OFF  = RZ_OFF + 64;

    extern __shared__ float smf[];
    int* smi = (int*)smf;

    cg::cluster_group cluster = cg::this_cluster();
    const int rank  = (int)cluster.block_rank();
    const int batch = blockIdx.x / CLUSTER;
    const int tid   = threadIdx.x;
    const int c     = tid & (kNX - 1);      // column 0..255
    const int g     = tid >> 8;             // 0 = top half of slab, 1 = bottom half
    const int lane  = c & 31;
    const int wc    = c >> 5;               // warp-column 0..7
    const int gz0   = rank * kRows + g * R; // first global row of this strip

    // ---- init: zero edge buffers (both parities), wavelet, receiver coords ----
    for (int i = tid; i < HE_OFF + 64 * R; i += kThreads) smf[i] = 0.0f;
    if (tid < kNT) smf[WAV_OFF + tid] = x[batch * kNT + tid];
    if (tid < kNREC) {
        smi[RZ_OFF + tid] = rec_loc[(batch * kNREC + tid) * 2 + 0];
        smi[RX_OFF + tid] = rec_loc[(batch * kNREC + tid) * 2 + 1];
    }
    __syncthreads();

    // ---- static receiver ownership: 64-bit mask of receivers living in my strip ----
    uint64_t rmask = 0;
    for (int k = 0; k < kNREC; k++) {
        int rz = smi[RZ_OFF + k], rx = smi[RX_OFF + k];
        if (rx == c && rz >= gz0 && rz < gz0 + R) rmask |= 1ull << k;
    }

    // ---- static source ownership ----
    const int sz = src_loc[batch * 2 + 0];
    const int sx = src_loc[batch * 2 + 1];
    const int srcIdx = (c == sx && sz >= gz0 && sz < gz0 + R) ? (sz - gz0) : -1;

    // ---- register-resident field + coefficients; dead cells get c2=0 (stay 0 forever) ----
    float c2[R], h[R], hp[R];
    const bool activeCol = (c > 0) && (c < kNX - 1);
#pragma unroll
    for (int i = 0; i < R; i++) {
        float v  = vp[(gz0 + i) * kNX + c];
        bool dead = !activeCol
                 || (rank == 0 && g == 0 && i == 0)                // global row 0
                 || (rank == CLUSTER - 1 && g == 1 && i == R - 1); // global row NZ-1
        c2[i] = dead ? 0.0f : v * v * kDT2;
        h[i] = 0.0f; hp[i] = 0.0f;
    }

    const int prevRank = (rank == 0) ? 0 : rank - 1;
    const int nextRank = (rank == CLUSTER - 1) ? rank : rank + 1;
    const float* prevV = (const float*)cluster.map_shared_rank((void*)smf, prevRank);
    const float* nextV = (const float*)cluster.map_shared_rank((void*)smf, nextRank);

    cluster.sync();   // edge buffers zeroed cluster-wide before first halo read

    float* outB = out + batch * kNT * kNREC;

    // one time step: hc = current field, hn = previous field (overwritten with new)
    auto body = [&](float (&hc)[R], float (&hn)[R], int t) {
        const int p = t & 1, q = p ^ 1;
        const float inj = kDT2 * smf[WAV_OFF + t];

        // strip-edge halos (remote = DSMEM; issued first, consumed in the LAST row computed)
        float topH, botH;
        if (g == 0) { topH = prevV[p * 1024 + 3 * 256 + c]; botH = smf[p * 1024 + 2 * 256 + c]; }
        else        { topH = smf[p * 1024 + 1 * 256 + c];   botH = nextV[p * 1024 + 0 * 256 + c]; }

        const int heL = HE_OFF + ((p * 2 + g) * 8 + ((wc > 0) ? wc - 1 : 0)) * R * 2;
        const int heR = HE_OFF + ((p * 2 + g) * 8 + ((wc < 7) ? wc + 1 : 7)) * R * 2;

        // rows: g0 descends (remote topH used last), g1 ascends (remote botH used last)
        if (g == 0) {
#pragma unroll
            for (int j = 0; j < R; j++) {
                const int i = R - 1 - j;   // constant after unroll
                float up = (i > 0)     ? hc[i - 1] : topH;
                float dn = (i < R - 1) ? hc[i + 1] : botH;
                float l  = __shfl_up_sync(0xffffffffu, hc[i], 1);
                if (lane == 0)  l = smf[heL + i * 2 + 1];
                float r  = __shfl_down_sync(0xffffffffu, hc[i], 1);
                if (lane == 31) r = smf[heR + i * 2 + 0];
                float lap = ((up + dn) + (l + r) - 4.0f * hc[i]) * kInvDH2;
                hn[i] = fmaf(c2[i], lap, 2.0f * hc[i] - hn[i]);
            }
        } else {
#pragma unroll
            for (int i = 0; i < R; i++) {
                float up = (i > 0)     ? hc[i - 1] : topH;
                float dn = (i < R - 1) ? hc[i + 1] : botH;
                float l  = __shfl_up_sync(0xffffffffu, hc[i], 1);
                if (lane == 0)  l = smf[heL + i * 2 + 1];
                float r  = __shfl_down_sync(0xffffffffu, hc[i], 1);
                if (lane == 31) r = smf[heR + i * 2 + 0];
                float lap = ((up + dn) + (l + r) - 4.0f * hc[i]) * kInvDH2;
                hn[i] = fmaf(c2[i], lap, 2.0f * hc[i] - hn[i]);
            }
        }

        // source injection BEFORE any publish/gather (source may sit on an edge row)
        if (srcIdx >= 0) {
#pragma unroll
            for (int i = 0; i < R; i++) if (i == srcIdx) hn[i] += inj;
        }

        // publish strip-edge rows of the NEW field (read by neighbors / other half next step)
        {
            const int q4 = q * 1024;
            if (g == 0) { smf[q4 + 0 * 256 + c] = hn[0]; smf[q4 + 1 * 256 + c] = hn[R - 1]; }
            else        { smf[q4 + 2 * 256 + c] = hn[0]; smf[q4 + 3 * 256 + c] = hn[R - 1]; }
        }
        CLUSTER_ARRIVE();   // release: my vEdge[q] published

        // publish warp-edge columns (intra-CTA only; ordered by __syncthreads below)
        if (lane == 0 || lane == 31) {
            const int e = (lane == 31);
            const int base = HE_OFF + ((q * 2 + g) * 8 + wc) * R * 2 + e;
#pragma unroll
            for (int i = 0; i < R; i++) smf[base + i * 2] = hn[i];
        }

        // receiver gather straight from registers (unrolled SEL: no dynamic indexing)
        uint64_t m = rmask;
        while (m) {
            int k = __ffsll((long long)m) - 1; m &= m - 1;
            int idx = smi[RZ_OFF + k] - gz0;
            float v = hn[0];
#pragma unroll
            for (int i = 1; i < R; i++) if (idx == i) v = hn[i];
            outB[t * kNREC + k] = v;
        }

        __syncthreads();    // intra-CTA: hEdge[q] + local vEdge[q] visible
        CLUSTER_WAIT();     // acquire: neighbors' vEdge[q] visible
    };

    for (int t = 0; t < kNT; t += 2) {
        body(h,  hp, t);        // new field lands in hp
        body(hp, h,  t + 1);    // roles swapped: zero-cost ping-pong
    }
}

extern "C" void kernel_launch(void* const* d_in, const int* in_sizes, int n_in,
                              void* d_out, int out_size)
{
    (void)in_sizes; (void)n_in; (void)out_size;
    const float* x   = (const float*)d_in[0];
    const float* vp  = (const float*)d_in[1];
    const int*   src = (const int*)d_in[2];
    const int*   rec = (const int*)d_in[3];
    float*       out = (float*)d_out;

    cudaFuncSetAttribute(wave_fd_kernel<16>,
                         cudaFuncAttributeMaxDynamicSharedMemorySize, smem_bytes(16));
    cudaFuncSetAttribute(wave_fd_kernel<16>,
                         cudaFuncAttributeNonPortableClusterSizeAllowed, 1);
    cudaFuncSetAttribute(wave_fd_kernel<8>,
                         cudaFuncAttributeMaxDynamicSharedMemorySize, smem_bytes(8));

    int maxCluster = 0;
    {
        cudaLaunchConfig_t probe = {};
        probe.gridDim          = dim3(kB * 16, 1, 1);
        probe.blockDim         = dim3(kThreads, 1, 1);
        probe.dynamicSmemBytes = smem_bytes(16);
        cudaOccupancyMaxPotentialClusterSize(&maxCluster, (const void*)wave_fd_kernel<16>, &probe);
    }

    cudaLaunchAttribute attr[1];
    attr[0].id = cudaLaunchAttributeClusterDimension;
    attr[0].val.clusterDim.y = 1;
    attr[0].val.clusterDim.z = 1;

    cudaLaunchConfig_t cfg = {};
    cfg.blockDim = dim3(kThreads, 1, 1);
    cfg.stream   = 0;
    cfg.attrs    = attr;
    cfg.numAttrs = 1;

    if (maxCluster >= 16) {
        cfg.gridDim              = dim3(kB * 16, 1, 1);
        cfg.dynamicSmemBytes     = smem_bytes(16);
        attr[0].val.clusterDim.x = 16;
        cudaLaunchKernelEx(&cfg, wave_fd_kernel<16>, x, vp, src, rec, out);
    } else {
        cfg.gridDim              = dim3(kB * 8, 1, 1);
        cfg.dynamicSmemBytes     = smem_bytes(8);
        attr[0].val.clusterDim.x = 8;
        cudaLaunchKernelEx(&cfg, wave_fd_kernel<8>, x, vp, src, rec, out);
    }
}

// round 8
// speedup vs baseline: 1.3513x; 1.3513x over previous
#include <cuda_runtime.h>
#include <cooperative_groups.h>

namespace cg = cooperative_groups;

namespace {
constexpr int   kB       = 8;
constexpr int   kNT      = 256;
constexpr int   kNZ      = 256;
constexpr int   kNX      = 256;
constexpr int   kNREC    = 64;
constexpr int   kThreads = 1024;              // 4 groups of 256 (column = tid & 255)
constexpr int   kGroups  = kThreads / kNX;    // 4 row-groups per CTA
constexpr float kDT2     = 1.0e-6f;           // DT*DT
constexpr float kInvDH2  = 0.01f;             // 1/(DH*DH)

constexpr int smem_floats(int cluster) {
    int rows = kNZ / cluster;
    int bufFloats = rows * kNX;
    return 2 * bufFloats + kNT + 64 + 64 + 4;
}
constexpr int smem_bytes(int cluster) { return smem_floats(cluster) * 4; }
}

template <int CLUSTER>
__global__ void __launch_bounds__(kThreads, 1)
wave_fd_kernel(const float* __restrict__ x,
               const float* __restrict__ vp,
               const int*   __restrict__ src_loc,
               const int*   __restrict__ rec_loc,
               float*       __restrict__ out)
{
    constexpr int kRows = kNZ / CLUSTER;          // rows per CTA (16 @ cluster16)
    constexpr int kPer  = kRows / kGroups;        // rows per thread (4 @ cluster16)
    constexpr int kBufFloats = kRows * kNX;
    constexpr int kWavOff = 2 * kBufFloats;
    constexpr int kIntOff = kWavOff + kNT;

    extern __shared__ float sm[];
    float* bufA   = sm;
    float* bufB   = sm + kBufFloats;
    float* wav    = sm + kWavOff;
    int*   recOff = (int*)(sm + kIntOff);
    int*   recK   = recOff + 64;
    int*   recCnt = recK + 64;

    cg::cluster_group cluster = cg::this_cluster();
    const int rank  = (int)cluster.block_rank();
    const int batch = blockIdx.x / CLUSTER;
    const int tid   = threadIdx.x;
    const int c     = tid & (kNX - 1);            // column 0..255
    const int g     = tid >> 8;                   // row-group 0..kGroups-1
    const int gz0   = rank * kRows + g * kPer;    // first global row of this strip

    // ---- init: zero ping-pong buffers, wavelet, receiver list ----
    for (int i = tid; i < 2 * kBufFloats; i += kThreads) sm[i] = 0.0f;
    if (tid < kNT) wav[tid] = x[batch * kNT + tid];
    if (tid == 0) *recCnt = 0;
    __syncthreads();
    if (tid < kNREC) {
        int rz = rec_loc[(batch * kNREC + tid) * 2 + 0];
        int rx = rec_loc[(batch * kNREC + tid) * 2 + 1];
        if (rz >= rank * kRows && rz < (rank + 1) * kRows) {
            int slot = atomicAdd(recCnt, 1);
            recOff[slot] = (rz - rank * kRows) * kNX + rx;
            recK[slot]   = tid;
        }
    }
    __syncthreads();
    const int cnt = *recCnt;

    // ---- source ownership ----
    const int  sz     = src_loc[batch * 2 + 0];
    const int  sx     = src_loc[batch * 2 + 1];
    const bool isSrc  = (c == sx) && (sz >= gz0) && (sz < gz0 + kPer);
    const int  srcOff = (sz - rank * kRows) * kNX + c;

    // ---- per-cell coefficients and h^{t-1} in registers ----
    float c2[kPer], h2[kPer];
#pragma unroll
    for (int i = 0; i < kPer; i++) {
        float v = vp[(gz0 + i) * kNX + c];
        c2[i] = v * v * kDT2;
        h2[i] = 0.0f;
    }

    const bool active    = (c > 0) && (c < kNX - 1);
    const bool topGrp    = (g == 0);
    const bool botGrp    = (g == kGroups - 1);
    const bool skipFirst = (rank == 0) && topGrp;              // global row 0
    const bool skipLast  = (rank == CLUSTER - 1) && botGrp;    // global row NZ-1

    // ---- DSMEM neighbor pointers (clamped at cluster edges) ----
    const int prevRank = (rank == 0) ? 0 : rank - 1;
    const int nextRank = (rank == CLUSTER - 1) ? rank : rank + 1;
    const float* prevA = cluster.map_shared_rank(bufA, prevRank);
    const float* prevB = cluster.map_shared_rank(bufB, prevRank);
    const float* nextA = cluster.map_shared_rank(bufA, nextRank);
    const float* nextB = cluster.map_shared_rank(bufB, nextRank);

    cluster.sync();   // buffers zeroed everywhere before first halo read

    const int strip = g * kPer * kNX + c;

    for (int t = 0; t < kNT; t++) {
        const float* cur     = (t & 1) ? bufB : bufA;
        float*       nxt     = (t & 1) ? bufA : bufB;
        const float* prevCur = (t & 1) ? prevB : prevA;
        const float* nextCur = (t & 1) ? nextB : nextA;

        if (active) {
            const float* cb = cur + strip;
            float*       nb = nxt + strip;

            // Remote halos issued up-front (only outermost groups touch DSMEM);
            // consumption is rows later, covered by 32-warp interleave.
            float haloTop = 0.0f, haloBot = 0.0f;
            if (topGrp) haloTop = prevCur[(kRows - 1) * kNX + c];
            if (botGrp) haloBot = nextCur[c];

            float cm1 = topGrp ? haloTop : cb[-kNX];
            float c0  = cb[0];
#pragma unroll
            for (int i = 0; i < kPer; i++) {
                float cp1;
                if (i < kPer - 1)  cp1 = cb[(i + 1) * kNX];
                else if (botGrp)   cp1 = haloBot;
                else               cp1 = cb[kPer * kNX];   // next group's first row (local)
                float l   = cb[i * kNX - 1];
                float r   = cb[i * kNX + 1];
                float lap = ((cm1 + cp1) + (l + r) - 4.0f * c0) * kInvDH2;
                float hn  = fmaf(c2[i], lap, 2.0f * c0 - h2[i]);
                h2[i] = c0;
                bool store = true;
                if (i == 0        && skipFirst) store = false;
                if (i == kPer - 1 && skipLast)  store = false;
                if (store) nb[i * kNX] = hn;
                cm1 = c0; c0 = cp1;
            }
            if (isSrc) nxt[srcOff] += kDT2 * wav[t];
        }

        cluster.sync();   // single barrier per step: nxt complete cluster-wide

        // gather AFTER the sync; this buffer is not rewritten until t+2,
        // which is ordered after sync(t+1) > this gather.
        if (tid < cnt)
            out[(batch * kNT + t) * kNREC + recK[tid]] = nxt[recOff[tid]];
    }
}

extern "C" void kernel_launch(void* const* d_in, const int* in_sizes, int n_in,
                              void* d_out, int out_size)
{
    (void)in_sizes; (void)n_in; (void)out_size;
    const float* x   = (const float*)d_in[0];
    const float* vp  = (const float*)d_in[1];
    const int*   src = (const int*)d_in[2];
    const int*   rec = (const int*)d_in[3];
    float*       out = (float*)d_out;

    cudaFuncSetAttribute(wave_fd_kernel<16>,
                         cudaFuncAttributeMaxDynamicSharedMemorySize, smem_bytes(16));
    cudaFuncSetAttribute(wave_fd_kernel<16>,
                         cudaFuncAttributeNonPortableClusterSizeAllowed, 1);
    cudaFuncSetAttribute(wave_fd_kernel<8>,
                         cudaFuncAttributeMaxDynamicSharedMemorySize, smem_bytes(8));

    int maxCluster = 0;
    {
        cudaLaunchConfig_t probe = {};
        probe.gridDim          = dim3(kB * 16, 1, 1);
        probe.blockDim         = dim3(kThreads, 1, 1);
        probe.dynamicSmemBytes = smem_bytes(16);
        cudaOccupancyMaxPotentialClusterSize(&maxCluster, (const void*)wave_fd_kernel<16>, &probe);
    }

    cudaLaunchAttribute attr[1];
    attr[0].id = cudaLaunchAttributeClusterDimension;
    attr[0].val.clusterDim.y = 1;
    attr[0].val.clusterDim.z = 1;

    cudaLaunchConfig_t cfg = {};
    cfg.blockDim = dim3(kThreads, 1, 1);
    cfg.stream   = 0;
    cfg.attrs    = attr;
    cfg.numAttrs = 1;

    if (maxCluster >= 16) {
        cfg.gridDim              = dim3(kB * 16, 1, 1);
        cfg.dynamicSmemBytes     = smem_bytes(16);
        attr[0].val.clusterDim.x = 16;
        cudaLaunchKernelEx(&cfg, wave_fd_kernel<16>, x, vp, src, rec, out);
    } else {
        cfg.gridDim              = dim3(kB * 8, 1, 1);
        cfg.dynamicSmemBytes     = smem_bytes(8);
        attr[0].val.clusterDim.x = 8;
        cudaLaunchKernelEx(&cfg, wave_fd_kernel<8>, x, vp, src, rec, out);
    }
}

// round 9
// speedup vs baseline: 1.9331x; 1.4306x over previous
#include <cuda_runtime.h>
#include <cooperative_groups.h>

namespace cg = cooperative_groups;

namespace {
constexpr int   kB       = 8;
constexpr int   kNT      = 256;
constexpr int   kNZ      = 256;
constexpr int   kNX      = 256;
constexpr int   kNREC    = 64;
constexpr int   kThreads = 512;               // column = tid&255, group = tid>>8
constexpr float kDT2     = 1.0e-6f;           // DT*DT
constexpr float kInvDH2  = 0.01f;             // 1/(DH*DH)

constexpr int smem_floats(int cluster) {
    int rows = kNZ / cluster;
    int buf  = rows * kNX;
    // 4 rotating field buffers | sA(256) sB(256) | wav(256) | recOff(64) recK(64) recCnt+pad(4)
    return 4 * buf + 512 + kNT + 64 + 64 + 4;
}
constexpr int smem_bytes(int cluster) { return smem_floats(cluster) * 4; }
}

template <int CLUSTER>
__global__ void __launch_bounds__(kThreads, 1)
wave_fd_kernel(const float* __restrict__ x,
               const float* __restrict__ vp,
               const int*   __restrict__ src_loc,
               const int*   __restrict__ rec_loc,
               float*       __restrict__ out)
{
    constexpr int kRows = kNZ / CLUSTER;      // rows per CTA
    constexpr int H     = kRows / 2;          // rows per thread
    constexpr int BUF   = kRows * kNX;        // floats per field buffer
    constexpr int SA    = 4 * BUF;            // staged prev-CTA cur row (kRows-1)
    constexpr int SB    = SA + 256;           // staged next-CTA cur row 0
    constexpr int WAV   = SB + 256;
    constexpr int ROFF  = WAV + kNT;
    constexpr int RK    = ROFF + 64;
    constexpr int RCNT  = RK + 64;

    extern __shared__ float sm[];
    int* smi = (int*)sm;

    cg::cluster_group cluster = cg::this_cluster();
    const int rank  = (int)cluster.block_rank();
    const int batch = blockIdx.x / CLUSTER;
    const int tid   = threadIdx.x;
    const int c     = tid & (kNX - 1);        // column
    const int g     = tid >> 8;               // 0 = top half, 1 = bottom half
    const int r0    = rank * kRows;           // CTA's first global row
    const int gz0   = r0 + g * H;             // my first global row

    // ---- init: zero all 4 field buffers + stage rows; wavelet; receiver list ----
    for (int i = tid; i < 4 * BUF + 512; i += kThreads) sm[i] = 0.0f;
    if (tid < kNT) sm[WAV + tid] = x[batch * kNT + tid];
    if (tid == 0) smi[RCNT] = 0;
    __syncthreads();
    if (tid < kNREC) {
        int rz = rec_loc[(batch * kNREC + tid) * 2 + 0];
        int rx = rec_loc[(batch * kNREC + tid) * 2 + 1];
        if (rz >= r0 && rz < r0 + kRows) {
            int slot = atomicAdd(&smi[RCNT], 1);
            smi[ROFF + slot] = (rz - r0) * kNX + rx;
            smi[RK   + slot] = tid;
        }
    }
    __syncthreads();
    const int cnt = smi[RCNT];

    // ---- source ownership (src is always interior: rows/cols 4..251) ----
    const int  sz = src_loc[batch * 2 + 0];
    const int  sx = src_loc[batch * 2 + 1];
    const bool isCol  = (c == sx);
    const int  srcRow = (isCol && sz >= gz0 && sz < gz0 + H) ? (sz - gz0) : -100;
    const bool srcExt = isCol && (g == 0 ? (sz == r0 - 1) : (sz == r0 + kRows));

    // ---- per-cell coefficients (c2=0 marks dead cells that stay 0 forever) ----
    float c2[H], c2e;
    const bool active = (c > 0) && (c < kNX - 1);
#pragma unroll
    for (int i = 0; i < H; i++) {
        int gz = gz0 + i;
        float v = vp[gz * kNX + c];
        bool dead = !active || gz == 0 || gz == kNZ - 1;
        c2[i] = dead ? 0.0f : v * v * kDT2;
    }
    {   // ghost-row coefficient (row r0-1 for g0, row r0+kRows for g1)
        int ge   = (g == 0) ? r0 - 1 : r0 + kRows;
        bool dE  = !active || ge <= 0 || ge >= kNZ - 1;
        int gec  = ge < 0 ? 0 : (ge > kNZ - 1 ? kNZ - 1 : ge);
        float ve = vp[gec * kNX + c];
        c2e = dE ? 0.0f : ve * ve * kDT2;
    }

    // ---- register-resident own rows: hE = even-time field, hO = odd-time field ----
    float hE[H], hO[H], extI = 0.0f;
#pragma unroll
    for (int i = 0; i < H; i++) { hE[i] = 0.0f; hO[i] = 0.0f; }

    const int prevRank = (rank == 0) ? 0 : rank - 1;
    const int nextRank = (rank == CLUSTER - 1) ? rank : rank + 1;
    const float* prevS = (const float*)cluster.map_shared_rank((void*)sm, prevRank);
    const float* nextS = (const float*)cluster.map_shared_rank((void*)sm, nextRank);

    cluster.sync();   // all buffers zeroed cluster-wide

    float* outB = out + batch * kNT * kNREC;

    // Superstep s advances t=2s -> t+2 with ONE cluster.sync.
    // Buffer rotation: cur=buf[t&3] (h^t), prv=buf[(t+3)&3] (h^{t-1}),
    // bufI=buf[(t+1)&3] (h^{t+1}), bufO=buf[(t+2)&3] (h^{t+2}).
    // bufO's old content h^{t-2} is dead; neighbor reads of cur/prv of step s
    // complete before sync(s), and those buffers are first rewritten after it.
    for (int s = 0; s < kNT / 2; s++) {
        const int t = 2 * s;
        const float* cur  = sm + (t & 3) * BUF;
        float*       bufI = sm + ((t + 1) & 3) * BUF;
        float*       bufO = sm + ((t + 2) & 3) * BUF;
        const float* pC   = prevS + (t & 3) * BUF;
        const float* pP   = prevS + ((t + 3) & 3) * BUF;
        const float* nC   = nextS + (t & 3) * BUF;
        const float* nP   = nextS + ((t + 3) & 3) * BUF;

        // ---- stage radius-2 remote halo (3 values/thread; 1 row via smem for l/r) ----
        float a0, a1, ap;
        if (g == 0) {
            a0 = pC[(kRows - 1) * kNX + c];   // h^t   row r0-1 (ghost center)
            a1 = pC[(kRows - 2) * kNX + c];   // h^t   row r0-2 (ghost's up)
            ap = pP[(kRows - 1) * kNX + c];   // h^t-1 row r0-1
            sm[SA + c] = a0;
        } else {
            a0 = nC[c];                       // h^t   row r0+kRows
            a1 = nC[kNX + c];                 // h^t   row r0+kRows+1
            ap = nP[c];                       // h^t-1 row r0+kRows
            sm[SB + c] = a0;
        }
        __syncthreads();                      // staged rows visible

        const float inj1 = kDT2 * sm[WAV + t];
        const float inj2 = kDT2 * sm[WAV + t + 1];

        // ---- phase 1: intermediate h^{t+1} on rows [r0-1, r0+kRows] ----
        if (active) {
            if (g == 0) {
                {   // ghost row r0-1 -> register extI only (phase 2 reads center col only)
                    float lap = ((a1 + hE[0]) + (sm[SA + c - 1] + sm[SA + c + 1]) - 4.0f * a0) * kInvDH2;
                    float hn  = fmaf(c2e, lap, 2.0f * a0 - ap);
                    if (srcExt) hn += inj1;
                    extI = hn;
                }
#pragma unroll
                for (int i = 0; i < H; i++) {
                    float up = (i == 0)     ? a0 : hE[i - 1];
                    float dn = (i == H - 1) ? cur[H * kNX + c] : hE[i + 1];  // g1's first row
                    float l  = cur[i * kNX + c - 1];
                    float r  = cur[i * kNX + c + 1];
                    float lap = ((up + dn) + (l + r) - 4.0f * hE[i]) * kInvDH2;
                    float hn  = fmaf(c2[i], lap, 2.0f * hE[i] - hO[i]);
                    if (i == srcRow) hn += inj1;
                    hO[i] = hn;
                    bufI[i * kNX + c] = hn;
                }
            } else {
#pragma unroll
                for (int i = 0; i < H; i++) {
                    float up = (i == 0)     ? cur[(H - 1) * kNX + c] : hE[i - 1]; // g0's last row
                    float dn = (i == H - 1) ? a0 : hE[i + 1];
                    float l  = cur[(H + i) * kNX + c - 1];
                    float r  = cur[(H + i) * kNX + c + 1];
                    float lap = ((up + dn) + (l + r) - 4.0f * hE[i]) * kInvDH2;
                    float hn  = fmaf(c2[i], lap, 2.0f * hE[i] - hO[i]);
                    if (i == srcRow) hn += inj1;
                    hO[i] = hn;
                    bufI[(H + i) * kNX + c] = hn;
                }
                {   // ghost row r0+kRows
                    float lap = ((hE[H - 1] + a1) + (sm[SB + c - 1] + sm[SB + c + 1]) - 4.0f * a0) * kInvDH2;
                    float hn  = fmaf(c2e, lap, 2.0f * a0 - ap);
                    if (srcExt) hn += inj1;
                    extI = hn;
                }
            }
        }
        __syncthreads();                      // bufI complete CTA-wide

        // receiver gather for step t (reads bufI, own CTA)
        if (tid < cnt)
            outB[t * kNREC + smi[RK + tid]] = bufI[smi[ROFF + tid]];

        // ---- phase 2: h^{t+2} on my rows from bufI (+ ghost regs) and hE (=h^t) ----
        if (active) {
            if (g == 0) {
#pragma unroll
                for (int i = 0; i < H; i++) {
                    float up = (i == 0)     ? extI : hO[i - 1];
                    float dn = (i == H - 1) ? bufI[H * kNX + c] : hO[i + 1];
                    float l  = bufI[i * kNX + c - 1];
                    float r  = bufI[i * kNX + c + 1];
                    float lap = ((up + dn) + (l + r) - 4.0f * hO[i]) * kInvDH2;
                    float hn  = fmaf(c2[i], lap, 2.0f * hO[i] - hE[i]);
                    if (i == srcRow) hn += inj2;
                    hE[i] = hn;
                    bufO[i * kNX + c] = hn;
                }
            } else {
#pragma unroll
                for (int i = 0; i < H; i++) {
                    float up = (i == 0)     ? bufI[(H - 1) * kNX + c] : hO[i - 1];
                    float dn = (i == H - 1) ? extI : hO[i + 1];
                    float l  = bufI[(H + i) * kNX + c - 1];
                    float r  = bufI[(H + i) * kNX + c + 1];
                    float lap = ((up + dn) + (l + r) - 4.0f * hO[i]) * kInvDH2;
                    float hn  = fmaf(c2[i], lap, 2.0f * hO[i] - hE[i]);
                    if (i == srcRow) hn += inj2;
                    hE[i] = hn;
                    bufO[(H + i) * kNX + c] = hn;
                }
            }
        }

        cluster.sync();   // publish bufI (h^{t+1}) + bufO (h^{t+2}); orders bufO for gather

        // receiver gather for step t+1 (bufO not rewritten until superstep s+2,
        // which is ordered after sync(s+1) > this read)
        if (tid < cnt)
            outB[(t + 1) * kNREC + smi[RK + tid]] = bufO[smi[ROFF + tid]];
    }
}

extern "C" void kernel_launch(void* const* d_in, const int* in_sizes, int n_in,
                              void* d_out, int out_size)
{
    (void)in_sizes; (void)n_in; (void)out_size;
    const float* x   = (const float*)d_in[0];
    const float* vp  = (const float*)d_in[1];
    const int*   src = (const int*)d_in[2];
    const int*   rec = (const int*)d_in[3];
    float*       out = (float*)d_out;

    cudaFuncSetAttribute(wave_fd_kernel<16>,
                         cudaFuncAttributeMaxDynamicSharedMemorySize, smem_bytes(16));
    cudaFuncSetAttribute(wave_fd_kernel<16>,
                         cudaFuncAttributeNonPortableClusterSizeAllowed, 1);
    cudaFuncSetAttribute(wave_fd_kernel<8>,
                         cudaFuncAttributeMaxDynamicSharedMemorySize, smem_bytes(8));

    int maxCluster = 0;
    {
        cudaLaunchConfig_t probe = {};
        probe.gridDim          = dim3(kB * 16, 1, 1);
        probe.blockDim         = dim3(kThreads, 1, 1);
        probe.dynamicSmemBytes = smem_bytes(16);
        cudaOccupancyMaxPotentialClusterSize(&maxCluster, (const void*)wave_fd_kernel<16>, &probe);
    }

    cudaLaunchAttribute attr[1];
    attr[0].id = cudaLaunchAttributeClusterDimension;
    attr[0].val.clusterDim.y = 1;
    attr[0].val.clusterDim.z = 1;

    cudaLaunchConfig_t cfg = {};
    cfg.blockDim = dim3(kThreads, 1, 1);
    cfg.stream   = 0;
    cfg.attrs    = attr;
    cfg.numAttrs = 1;

    if (maxCluster >= 16) {
        cfg.gridDim              = dim3(kB * 16, 1, 1);
        cfg.dynamicSmemBytes     = smem_bytes(16);
        attr[0].val.clusterDim.x = 16;
        cudaLaunchKernelEx(&cfg, wave_fd_kernel<16>, x, vp, src, rec, out);
    } else {
        cfg.gridDim              = dim3(kB * 8, 1, 1);
        cfg.dynamicSmemBytes     = smem_bytes(8);
        attr[0].val.clusterDim.x = 8;
        cudaLaunchKernelEx(&cfg, wave_fd_kernel<8>, x, vp, src, rec, out);
    }
}